// round 12
// baseline (speedup 1.0000x reference)
#include <cuda_runtime.h>
#include <math.h>
#include <stdint.h>

#define N_PTS 32
#define D_DIM 128
#define ITERS 20
#define EPSF  1e-7f
#define CLIPF 1e-7f
#define FULL  0xffffffffu
#define PI_F  3.14159265358979f
#define RSW   68              // smem row stride floats (272B; 272%128==16)

__device__ double g_acc;      // zero-init; finalize resets after each read

__global__ void finalize_kernel(float* out, float invG) {
    out[0] = (float)(g_acc * (double)invG);
    g_acc = 0.0;              // restore invariant for next graph replay
}

__device__ __forceinline__ float warp_sum(float v) {
#pragma unroll
    for (int k = 16; k; k >>= 1) v += __shfl_xor_sync(FULL, v, k);
    return v;
}

// acos via A&S 4.4.46, |err|<=2e-8
__device__ __forceinline__ float acos_poly(float t) {
    float u = fabsf(t);
    float p = fmaf(u, -0.0012624911f, 0.0066700901f);
    p = fmaf(u, p, -0.0170881256f);
    p = fmaf(u, p,  0.0308918810f);
    p = fmaf(u, p, -0.0501743046f);
    p = fmaf(u, p,  0.0889789874f);
    p = fmaf(u, p, -0.2145988016f);
    p = fmaf(u, p,  1.5707963050f);
    float r = sqrtf(1.0f - u) * p;
    return (t >= 0.0f) ? r : (PI_F - r);
}

// warp-level tf32 HMMA: D(16x8,f32) += A(16x8) * B(8x8)
__device__ __forceinline__ void mma_t(float d[4],
                                      uint32_t a0, uint32_t a1, uint32_t a2, uint32_t a3,
                                      uint32_t b0, uint32_t b1) {
    asm volatile(
        "mma.sync.aligned.m16n8k8.row.col.f32.tf32.tf32.f32 "
        "{%0,%1,%2,%3}, {%4,%5,%6,%7}, {%8,%9}, {%0,%1,%2,%3};"
        : "+f"(d[0]), "+f"(d[1]), "+f"(d[2]), "+f"(d[3])
        : "r"(a0), "r"(a1), "r"(a2), "r"(a3), "r"(b0), "r"(b1));
}

// ===== Fused: tf32-HMMA Gram (1 warp/group) + Karcher iters in dot space ====
__global__ __launch_bounds__(32, 16) void karcher_fused(const float* __restrict__ X) {
    __shared__ float Xs[N_PTS * RSW];   // 8704 B staging; reused for G (32x33)

    const int g    = blockIdx.x;
    const int lane = threadIdx.x;
    const int rr   = lane >> 2;         // fragment row group 0..7
    const int c    = lane & 3;          // fragment col-in-quad 0..3
    const int lrow = lane >> 4;         // staging: 16 lanes x 2 rows
    const int ltile = lane & 15;

    const float4* __restrict__ Xg = (const float4*)(X + (size_t)g * (N_PTS * D_DIM));

    // 6 output tiles (m16n8): (mi,ni) = (0,0)(0,1)(1,0)(1,1)(1,2)(1,3)
    float d[6][4];
#pragma unroll
    for (int t = 0; t < 6; t++)
#pragma unroll
        for (int e = 0; e < 4; e++) d[t][e] = 0.0f;

#pragma unroll 1
    for (int pass = 0; pass < 2; pass++) {
        // ---- stage 32 x 64 f32 (raw bits; HW truncates to tf32) ----
#pragma unroll
        for (int i = 0; i < 16; i++) {
            int row = 2 * i + lrow;
            float4 v = __ldg(&Xg[row * (D_DIM / 4) + pass * 16 + ltile]);
            *(float4*)&Xs[row * RSW + 4 * ltile] = v;
        }
        __syncwarp();

        // ---- 8 k-steps: 8 shared fragment loads feed both A and B ----
        const float* p = &Xs[rr * RSW + c];
#pragma unroll
        for (int s = 0; s < 8; s++) {
            const float* q = p + 8 * s;
            uint32_t v00 = __float_as_uint(q[0]);
            uint32_t v01 = __float_as_uint(q[4]);
            uint32_t v10 = __float_as_uint(q[8  * RSW]);
            uint32_t v11 = __float_as_uint(q[8  * RSW + 4]);
            uint32_t v20 = __float_as_uint(q[16 * RSW]);
            uint32_t v21 = __float_as_uint(q[16 * RSW + 4]);
            uint32_t v30 = __float_as_uint(q[24 * RSW]);
            uint32_t v31 = __float_as_uint(q[24 * RSW + 4]);
            // A0 rows 0-15, A1 rows 16-31; Bj = rows 8j..8j+7
            mma_t(d[0], v00, v10, v01, v11, v00, v01);
            mma_t(d[1], v00, v10, v01, v11, v10, v11);
            mma_t(d[2], v20, v30, v21, v31, v00, v01);
            mma_t(d[3], v20, v30, v21, v31, v10, v11);
            mma_t(d[4], v20, v30, v21, v31, v20, v21);
            mma_t(d[5], v20, v30, v21, v31, v30, v31);
        }
        __syncwarp();                   // all fragment reads done before restage
    }

    // ---- scatter tiles (+ mirror of (1,0),(1,1)) into Gs = Xs, G[32][33] ----
    float* Gs = Xs;
    {
        const int mi[6] = {0, 0, 1, 1, 1, 1};
        const int ni[6] = {0, 1, 0, 1, 2, 3};
#pragma unroll
        for (int t = 0; t < 6; t++) {
            int r0 = 16 * mi[t] + rr, c0 = 8 * ni[t] + 2 * c;
            Gs[33 * r0 + c0]           = d[t][0];
            Gs[33 * r0 + c0 + 1]       = d[t][1];
            Gs[33 * (r0 + 8) + c0]     = d[t][2];
            Gs[33 * (r0 + 8) + c0 + 1] = d[t][3];
        }
#pragma unroll
        for (int t = 2; t < 4; t++) {   // mirror -> rows 0-15, cols 16-31
            int r0 = 16 + rr, c0 = 8 * ni[t] + 2 * c;
            Gs[33 * c0 + r0]           = d[t][0];
            Gs[33 * (c0 + 1) + r0]     = d[t][1];
            Gs[33 * c0 + r0 + 8]       = d[t][2];
            Gs[33 * (c0 + 1) + r0 + 8] = d[t][3];
        }
    }
    __syncwarp();

    // ---- lane reads its Gram column (conflict-free), normalize by diag ----
    float gr[N_PTS];
#pragma unroll
    for (int m = 0; m < N_PTS; m++) gr[m] = Gs[33 * m + lane];

    float rl = rsqrtf(fmaxf(gr[lane], 1e-24f));
#pragma unroll
    for (int m = 0; m < N_PTS; m++) {
        float rm = __shfl_sync(FULL, rl, m);
        gr[m] *= rl * rm;
    }

    // ---- init dots: dots0[n] = rowsum_n / sqrt(total) ----
    float rowsum = 0.0f;
#pragma unroll
    for (int m = 0; m < N_PTS; m++) rowsum += gr[m];
    float T = warp_sum(rowsum);
    float dot = rowsum * rsqrtf(fmaxf(T, 1e-24f));

    // ---- 20 Karcher iterations in dot space ----
    const float invN = 1.0f / N_PTS;
#pragma unroll 1
    for (int it = 0; it < ITERS; it++) {
        float t  = fminf(fmaxf(dot, -1.0f + CLIPF), 1.0f - CLIPF);
        float th = acos_poly(t);
        float st = sqrtf(fmaf(-t, t, 1.0f));
        float cc = __fdividef(th, st);

        float gc0 = 0.f, gc1 = 0.f, gc2 = 0.f, gc3 = 0.f;
#pragma unroll
        for (int m = 0; m < N_PTS; m += 4) {
            float c0 = __shfl_sync(FULL, cc, m);
            float c1 = __shfl_sync(FULL, cc, m + 1);
            float c2 = __shfl_sync(FULL, cc, m + 2);
            float c3 = __shfl_sync(FULL, cc, m + 3);
            gc0 = fmaf(gr[m],     c0, gc0);
            gc1 = fmaf(gr[m + 1], c1, gc1);
            gc2 = fmaf(gr[m + 2], c2, gc2);
            gc3 = fmaf(gr[m + 3], c3, gc3);
        }
        float gc = (gc0 + gc1) + (gc2 + gc3);

        // interleaved dual butterfly: s = c.dots, A2 = c^T G c
        float pa = cc * dot, pb = cc * gc;
#pragma unroll
        for (int k = 16; k; k >>= 1) {
            pa += __shfl_xor_sync(FULL, pa, k);
            pb += __shfl_xor_sync(FULL, pb, k);
        }
        float s = pa, A2 = pb;

        float vn2 = fmaxf(A2 - s * s, 0.0f) * (invN * invN);
        float vn  = fmaxf(sqrtf(vn2), EPSF);

        float sc = __fdividef(__sinf(vn), vn);
        float cs = __cosf(vn);

        dot = fmaf(cs, dot, sc * invN * fmaf(-s, dot, gc));
    }

    // ---- loss_g = sum_n acos(clip(dot_n))^2 ----
    {
        float t  = fminf(fmaxf(dot, -1.0f + CLIPF), 1.0f - CLIPF);
        float th = acos_poly(t);
        float l  = warp_sum(th * th);
        if (lane == 0) atomicAdd(&g_acc, (double)l);
    }
}

extern "C" void kernel_launch(void* const* d_in, const int* in_sizes, int n_in,
                              void* d_out, int out_size) {
    const float* X = (const float*)d_in[0];
    const int G = in_sizes[0] / (N_PTS * D_DIM);   // 8000 for (1000,8,32,128)

    karcher_fused<<<G, 32>>>(X);
    finalize_kernel<<<1, 1>>>((float*)d_out, 1.0f / (float)G);
}

// round 13
// speedup vs baseline: 1.5080x; 1.5080x over previous
#include <cuda_runtime.h>
#include <math.h>
#include <stdint.h>

#define N_PTS 32
#define D_DIM 128
#define ITERS 20
#define EPSF  1e-7f
#define CLIPF 1e-7f
#define FULL  0xffffffffu
#define PI_F  3.14159265358979f

__device__ double g_acc;      // zero-init; finalize resets after each read

__global__ void finalize_kernel(float* out, float invG) {
    out[0] = (float)(g_acc * (double)invG);
    g_acc = 0.0;              // restore invariant for next graph replay
}

__device__ __forceinline__ float warp_sum(float v) {
#pragma unroll
    for (int k = 16; k; k >>= 1) v += __shfl_xor_sync(FULL, v, k);
    return v;
}

// acos via A&S 4.4.46, |err|<=2e-8
__device__ __forceinline__ float acos_poly(float t) {
    float u = fabsf(t);
    float p = fmaf(u, -0.0012624911f, 0.0066700901f);
    p = fmaf(u, p, -0.0170881256f);
    p = fmaf(u, p,  0.0308918810f);
    p = fmaf(u, p, -0.0501743046f);
    p = fmaf(u, p,  0.0889789874f);
    p = fmaf(u, p, -0.2145988016f);
    p = fmaf(u, p,  1.5707963050f);
    float r = sqrtf(1.0f - u) * p;
    return (t >= 0.0f) ? r : (PI_F - r);
}

// warp-level tf32 HMMA: D(16x8,f32) += A(16x8) * B(8x8)
__device__ __forceinline__ void mma_t(float d[4],
                                      uint32_t a0, uint32_t a1, uint32_t a2, uint32_t a3,
                                      uint32_t b0, uint32_t b1) {
    asm volatile(
        "mma.sync.aligned.m16n8k8.row.col.f32.tf32.tf32.f32 "
        "{%0,%1,%2,%3}, {%4,%5,%6,%7}, {%8,%9}, {%0,%1,%2,%3};"
        : "+f"(d[0]), "+f"(d[1]), "+f"(d[2]), "+f"(d[3])
        : "r"(a0), "r"(a1), "r"(a2), "r"(a3), "r"(b0), "r"(b1));
}

// ===== Fused: tf32-HMMA Gram (direct LDG fragments) + Karcher dot-space =====
// k-slot permutation: fragment slot (c,h) takes column 8s + 2c + h. A and B use
// the identical map, and the k-dot is permutation-invariant, so G is exact.
__global__ __launch_bounds__(32, 26) void karcher_fused(const float* __restrict__ X) {
    __shared__ float Gs[N_PTS * 33];    // 4224 B: Gram scatter buffer only

    const int g    = blockIdx.x;
    const int lane = threadIdx.x;
    const int rr   = lane >> 2;         // fragment row 0..7
    const int c    = lane & 3;          // fragment k-quad 0..3

    // 6 output tiles (m16n8): (mi,ni) = (0,0)(0,1)(1,0)(1,1)(1,2)(1,3)
    float d[6][4];
#pragma unroll
    for (int t = 0; t < 6; t++)
#pragma unroll
        for (int e = 0; e < 4; e++) d[t][e] = 0.0f;

    // base: row rr, cols 2c..2c+1 (+8s); row-groups at +8,+16,+24 rows
    const float* __restrict__ base =
        X + (size_t)g * (N_PTS * D_DIM) + rr * D_DIM + 2 * c;

#pragma unroll
    for (int s = 0; s < 16; s++) {      // 16 k-steps of 8 cols cover K=128
        const float* q = base + 8 * s;
        float2 w0 = __ldg((const float2*)(q));
        float2 w1 = __ldg((const float2*)(q +  8 * D_DIM));
        float2 w2 = __ldg((const float2*)(q + 16 * D_DIM));
        float2 w3 = __ldg((const float2*)(q + 24 * D_DIM));
        uint32_t v00 = __float_as_uint(w0.x), v01 = __float_as_uint(w0.y);
        uint32_t v10 = __float_as_uint(w1.x), v11 = __float_as_uint(w1.y);
        uint32_t v20 = __float_as_uint(w2.x), v21 = __float_as_uint(w2.y);
        uint32_t v30 = __float_as_uint(w3.x), v31 = __float_as_uint(w3.y);
        // A0 rows 0-15, A1 rows 16-31; Bj = rows 8j..8j+7
        mma_t(d[0], v00, v10, v01, v11, v00, v01);
        mma_t(d[1], v00, v10, v01, v11, v10, v11);
        mma_t(d[2], v20, v30, v21, v31, v00, v01);
        mma_t(d[3], v20, v30, v21, v31, v10, v11);
        mma_t(d[4], v20, v30, v21, v31, v20, v21);
        mma_t(d[5], v20, v30, v21, v31, v30, v31);
    }

    // ---- scatter tiles (+ mirror of (1,0),(1,1)) into Gs, layout G[32][33] ----
    {
        const int mi[6] = {0, 0, 1, 1, 1, 1};
        const int ni[6] = {0, 1, 0, 1, 2, 3};
#pragma unroll
        for (int t = 0; t < 6; t++) {
            int r0 = 16 * mi[t] + rr, c0 = 8 * ni[t] + 2 * c;
            Gs[33 * r0 + c0]           = d[t][0];
            Gs[33 * r0 + c0 + 1]       = d[t][1];
            Gs[33 * (r0 + 8) + c0]     = d[t][2];
            Gs[33 * (r0 + 8) + c0 + 1] = d[t][3];
        }
#pragma unroll
        for (int t = 2; t < 4; t++) {   // mirror -> rows 0-15, cols 16-31
            int r0 = 16 + rr, c0 = 8 * ni[t] + 2 * c;
            Gs[33 * c0 + r0]           = d[t][0];
            Gs[33 * (c0 + 1) + r0]     = d[t][1];
            Gs[33 * c0 + r0 + 8]       = d[t][2];
            Gs[33 * (c0 + 1) + r0 + 8] = d[t][3];
        }
    }
    __syncwarp();

    // ---- lane reads its Gram column (conflict-free), normalize by diag ----
    float gr[N_PTS];
#pragma unroll
    for (int m = 0; m < N_PTS; m++) gr[m] = Gs[33 * m + lane];

    float rl = rsqrtf(fmaxf(gr[lane], 1e-24f));
#pragma unroll
    for (int m = 0; m < N_PTS; m++) {
        float rm = __shfl_sync(FULL, rl, m);
        gr[m] *= rl * rm;
    }

    // ---- init dots: dots0[n] = rowsum_n / sqrt(total) ----
    float rowsum = 0.0f;
#pragma unroll
    for (int m = 0; m < N_PTS; m++) rowsum += gr[m];
    float T = warp_sum(rowsum);
    float dot = rowsum * rsqrtf(fmaxf(T, 1e-24f));

    // ---- 20 Karcher iterations in dot space ----
    const float invN = 1.0f / N_PTS;
#pragma unroll 1
    for (int it = 0; it < ITERS; it++) {
        float t  = fminf(fmaxf(dot, -1.0f + CLIPF), 1.0f - CLIPF);
        float th = acos_poly(t);
        float st = sqrtf(fmaf(-t, t, 1.0f));
        float cc = __fdividef(th, st);

        float gc0 = 0.f, gc1 = 0.f, gc2 = 0.f, gc3 = 0.f;
#pragma unroll
        for (int m = 0; m < N_PTS; m += 4) {
            float c0 = __shfl_sync(FULL, cc, m);
            float c1 = __shfl_sync(FULL, cc, m + 1);
            float c2 = __shfl_sync(FULL, cc, m + 2);
            float c3 = __shfl_sync(FULL, cc, m + 3);
            gc0 = fmaf(gr[m],     c0, gc0);
            gc1 = fmaf(gr[m + 1], c1, gc1);
            gc2 = fmaf(gr[m + 2], c2, gc2);
            gc3 = fmaf(gr[m + 3], c3, gc3);
        }
        float gc = (gc0 + gc1) + (gc2 + gc3);

        // interleaved dual butterfly: s = c.dots, A2 = c^T G c
        float pa = cc * dot, pb = cc * gc;
#pragma unroll
        for (int k = 16; k; k >>= 1) {
            pa += __shfl_xor_sync(FULL, pa, k);
            pb += __shfl_xor_sync(FULL, pb, k);
        }
        float s = pa, A2 = pb;

        float vn2 = fmaxf(A2 - s * s, 0.0f) * (invN * invN);
        float vn  = fmaxf(sqrtf(vn2), EPSF);

        float sc = __fdividef(__sinf(vn), vn);
        float cs = __cosf(vn);

        dot = fmaf(cs, dot, sc * invN * fmaf(-s, dot, gc));
    }

    // ---- loss_g = sum_n acos(clip(dot_n))^2 ----
    {
        float t  = fminf(fmaxf(dot, -1.0f + CLIPF), 1.0f - CLIPF);
        float th = acos_poly(t);
        float l  = warp_sum(th * th);
        if (lane == 0) atomicAdd(&g_acc, (double)l);
    }
}

extern "C" void kernel_launch(void* const* d_in, const int* in_sizes, int n_in,
                              void* d_out, int out_size) {
    const float* X = (const float*)d_in[0];
    const int G = in_sizes[0] / (N_PTS * D_DIM);   // 8000 for (1000,8,32,128)

    karcher_fused<<<G, 32>>>(X);
    finalize_kernel<<<1, 1>>>((float*)d_out, 1.0f / (float)G);
}